// round 5
// baseline (speedup 1.0000x reference)
#include <cuda_runtime.h>
#include <cuda_bf16.h>
#include <math.h>

#define BATCH  64
#define NPATCH 196
#define NROWS  (BATCH * NPATCH)   // 12544
#define TDIM   1024
#define PDIM   768

// ---------------- scratch (static device allocations; no cudaMalloc) --------
__device__ float g_x [NROWS * TDIM];
__device__ float g_xn[NROWS * TDIM];
__device__ float g_S [BATCH * NPATCH * NPATCH];
__device__ float g_mean[BATCH * TDIM];
__device__ float g_lastW_unused; // placeholder

__device__ __nv_bfloat16 g_ph[NROWS * PDIM],  g_pl[NROWS * PDIM];     // patches split
__device__ __nv_bfloat16 g_xnh[NROWS * TDIM], g_xnl[NROWS * TDIM];
__device__ __nv_bfloat16 g_qh[NROWS * TDIM],  g_ql[NROWS * TDIM];
__device__ __nv_bfloat16 g_kh[NROWS * TDIM],  g_kl[NROWS * TDIM];
__device__ __nv_bfloat16 g_Gh[NROWS * TDIM],  g_Gl[NROWS * TDIM];
__device__ __nv_bfloat16 g_Ah[BATCH * NPATCH * NPATCH], g_Al[BATCH * NPATCH * NPATCH];
// transposed, split weights [N][K]
__device__ __nv_bfloat16 g_Weth[TDIM * PDIM], g_Wetl[TDIM * PDIM];
__device__ __nv_bfloat16 g_WQth[TDIM * TDIM], g_WQtl[TDIM * TDIM];
__device__ __nv_bfloat16 g_WKth[TDIM * TDIM], g_WKtl[TDIM * TDIM];
__device__ __nv_bfloat16 g_WVth[128 * 128],   g_WVtl[128 * 128];

// ---------------- helpers ----------------------------------------------------
__device__ __forceinline__ float warp_sum(float v) {
#pragma unroll
    for (int o = 16; o; o >>= 1) v += __shfl_xor_sync(0xffffffffu, v, o);
    return v;
}
__device__ __forceinline__ float warp_max(float v) {
#pragma unroll
    for (int o = 16; o; o >>= 1) v = fmaxf(v, __shfl_xor_sync(0xffffffffu, v, o));
    return v;
}
__device__ __forceinline__ void block_sum2(float& a, float& b, float* sm) {
    a = warp_sum(a);
    b = warp_sum(b);
    int w = threadIdx.x >> 5, l = threadIdx.x & 31;
    if (l == 0) { sm[w] = a; sm[8 + w] = b; }
    __syncthreads();
    float ta = 0.f, tb = 0.f;
#pragma unroll
    for (int i = 0; i < 8; i++) { ta += sm[i]; tb += sm[8 + i]; }
    a = ta; b = tb;
}
// split x into bf16 hi + lo
__device__ __forceinline__ void split1(float x, __nv_bfloat16& h, __nv_bfloat16& l) {
    h = __float2bfloat16_rn(x);
    l = __float2bfloat16_rn(x - __bfloat162float(h));
}
// split two floats, pack as (b<<16)|a into hi-word and lo-word
__device__ __forceinline__ void split_pack2(float a, float b, unsigned& hi, unsigned& lo) {
    __nv_bfloat16 ha, la, hb, lb;
    split1(a, ha, la);
    split1(b, hb, lb);
    hi = ((unsigned)__bfloat16_as_ushort(hb) << 16) | (unsigned)__bfloat16_as_ushort(ha);
    lo = ((unsigned)__bfloat16_as_ushort(lb) << 16) | (unsigned)__bfloat16_as_ushort(la);
}

// ---------------- weight split + transpose: W[K][N] -> hi/lo [N][K] ----------
__global__ void split_transpose_kernel(const float* __restrict__ W,
                                       __nv_bfloat16* __restrict__ Wh,
                                       __nv_bfloat16* __restrict__ Wl,
                                       int K, int N) {
    __shared__ float t[32][33];
    int n0 = blockIdx.x * 32, k0 = blockIdx.y * 32;
    int x = threadIdx.x, y = threadIdx.y;   // 32 x 8
#pragma unroll
    for (int i = 0; i < 32; i += 8)
        t[y + i][x] = W[(size_t)(k0 + y + i) * N + n0 + x];
    __syncthreads();
#pragma unroll
    for (int i = 0; i < 32; i += 8) {
        int n = n0 + y + i, k = k0 + x;
        __nv_bfloat16 h, l;
        split1(t[x][y + i], h, l);
        Wh[(size_t)n * K + k] = h;
        Wl[(size_t)n * K + k] = l;
    }
}

// ---------------- patchify + LayerNorm(768) -> split pairs -------------------
__global__ void patchify_ln_kernel(const float* __restrict__ img,
                                   const float* __restrict__ gam,
                                   const float* __restrict__ bet) {
    __shared__ float sv[PDIM];
    __shared__ float sred[16];
    int row = blockIdx.x;
    int b = row / NPATCH, n = row % NPATCH;
    int hp = n / 14, wp = n % 14;
    const float* base = img + (size_t)b * 3 * 224 * 224;
    int tid = threadIdx.x;
    float s = 0.f, s2 = 0.f;
#pragma unroll
    for (int i = 0; i < 3; i++) {
        int f = tid + i * 256;
        int p1 = f / 48, r = f % 48, p2 = r / 3, c = r % 3;
        float v = base[((size_t)c * 224 + hp * 16 + p1) * 224 + wp * 16 + p2];
        sv[f] = v; s += v; s2 += v * v;
    }
    block_sum2(s, s2, sred);
    float m = s * (1.f / 768.f);
    float rstd = rsqrtf(s2 * (1.f / 768.f) - m * m + 1e-5f);
#pragma unroll
    for (int i = 0; i < 3; i++) {
        int f = tid + i * 256;
        float v = (sv[f] - m) * rstd * gam[f] + bet[f];
        __nv_bfloat16 h, l;
        split1(v, h, l);
        g_ph[(size_t)row * PDIM + f] = h;
        g_pl[(size_t)row * PDIM + f] = l;
    }
}

// ---------------- LayerNorm(1024): f32 out + optional pos + optional pairs ---
__global__ void ln1024_kernel(const float* __restrict__ in, float* __restrict__ out,
                              const float* __restrict__ gam, const float* __restrict__ bet,
                              const float* __restrict__ pos,
                              __nv_bfloat16* __restrict__ oh, __nv_bfloat16* __restrict__ ol) {
    __shared__ float sred[16];
    int row = blockIdx.x, tid = threadIdx.x;
    const float4* ip = (const float4*)(in + (size_t)row * TDIM);
    float4 v = ip[tid];
    float s  = v.x + v.y + v.z + v.w;
    float s2 = v.x * v.x + v.y * v.y + v.z * v.z + v.w * v.w;
    block_sum2(s, s2, sred);
    float m = s * (1.f / 1024.f);
    float rstd = rsqrtf(s2 * (1.f / 1024.f) - m * m + 1e-5f);
    float4 gg = ((const float4*)gam)[tid];
    float4 bb = ((const float4*)bet)[tid];
    float4 o;
    o.x = (v.x - m) * rstd * gg.x + bb.x;
    o.y = (v.y - m) * rstd * gg.y + bb.y;
    o.z = (v.z - m) * rstd * gg.z + bb.z;
    o.w = (v.w - m) * rstd * gg.w + bb.w;
    if (pos) {
        int n = row % NPATCH;
        float4 p = ((const float4*)(pos + (size_t)n * TDIM))[tid];
        o.x += p.x; o.y += p.y; o.z += p.z; o.w += p.w;
    }
    ((float4*)(out + (size_t)row * TDIM))[tid] = o;
    if (oh) {
        unsigned h01, l01, h23, l23;
        split_pack2(o.x, o.y, h01, l01);
        split_pack2(o.z, o.w, h23, l23);
        ((uint2*)(oh + (size_t)row * TDIM))[tid] = make_uint2(h01, h23);
        ((uint2*)(ol + (size_t)row * TDIM))[tid] = make_uint2(l01, l23);
    }
}

// ---------------- softmax over 196, writes split pairs ------------------------
__global__ void softmax196_kernel() {
    __shared__ float sred[16];
    int row = blockIdx.x, tid = threadIdx.x;
    const float* p = g_S + (size_t)row * NPATCH;
    float v = (tid < NPATCH) ? p[tid] : -1e30f;
    float mx = warp_max(v);
    int w = tid >> 5, l = tid & 31;
    if (l == 0) sred[w] = mx;
    __syncthreads();
    float bm = -1e30f;
#pragma unroll
    for (int i = 0; i < 8; i++) bm = fmaxf(bm, sred[i]);
    float e = (tid < NPATCH) ? expf(v - bm) : 0.f;
    __syncthreads();
    float s = warp_sum(e);
    if (l == 0) sred[w] = s;
    __syncthreads();
    float bs = 0.f;
#pragma unroll
    for (int i = 0; i < 8; i++) bs += sred[i];
    if (tid < NPATCH) {
        float a = e / bs;
        __nv_bfloat16 h, lo;
        split1(a, h, lo);
        g_Ah[(size_t)row * NPATCH + tid] = h;
        g_Al[(size_t)row * NPATCH + tid] = lo;
    }
}

// ---------------- mean over tokens --------------------------------------------
__global__ void mean_kernel() {
    int b = blockIdx.x, tid = threadIdx.x;
    const float4* xp = (const float4*)(g_x + (size_t)b * NPATCH * TDIM);
    float4 acc = make_float4(0.f, 0.f, 0.f, 0.f);
    for (int n = 0; n < NPATCH; n++) {
        float4 v = xp[(size_t)n * 256 + tid];
        acc.x += v.x; acc.y += v.y; acc.z += v.z; acc.w += v.w;
    }
    const float inv = 1.f / 196.f;
    ((float4*)(g_mean + (size_t)b * TDIM))[tid] =
        make_float4(acc.x * inv, acc.y * inv, acc.z * inv, acc.w * inv);
}

// ---------------- bf16x3 tensor-core GEMM ------------------------------------
// C = alpha * (Ah+Al)(MxK) @ (Bh+Bl) + bias + resid   (drop lo*lo term)
// BL=0: B pairs are [N][K] row-major (pre-transposed weights / k / q-style)
// BL=1: B pairs are [K][N] row-major (G in A@G)
// OS: true -> write split bf16 pairs to Ch/Cl instead of f32 C
// block tile 128x128x32, 256 threads = 8 warps (2x4), warp tile 64x32.
template <int BL, bool OS>
__global__ void __launch_bounds__(256, 2) gemm_bf3(
    const __nv_bfloat16* __restrict__ Ah, const __nv_bfloat16* __restrict__ Al,
    const __nv_bfloat16* __restrict__ Bh, const __nv_bfloat16* __restrict__ Bl,
    float* __restrict__ C, __nv_bfloat16* __restrict__ Ch, __nv_bfloat16* __restrict__ Cl,
    int M, int N, int K,
    long long sA, long long sB, long long sC,
    float alpha, const float* __restrict__ bias, const float* __restrict__ resid)
{
    // rows of 32 k (=16 b32) padded to 20 b32 so frag LDS banks 20g+t are distinct
    __shared__ __align__(16) unsigned AsH[128][20], AsL[128][20];
    __shared__ __align__(16) unsigned BsH[128][20], BsL[128][20];

    const int bz = blockIdx.z;
    Ah += (size_t)bz * sA;  Al += (size_t)bz * sA;
    Bh += (size_t)bz * sB;  Bl += (size_t)bz * sB;
    if (!OS) { C += (size_t)bz * sC; if (resid) resid += (size_t)bz * sC; }
    else     { Ch += (size_t)bz * sC; Cl += (size_t)bz * sC; }

    const int tid  = threadIdx.x;
    const int lane = tid & 31, warp = tid >> 5;
    const int wm = warp >> 2, wn = warp & 3;
    const int g = lane >> 2, t = lane & 3;

    const int row0 = blockIdx.y * 128;
    const int col0 = blockIdx.x * 128;

    float c[4][4][4];
#pragma unroll
    for (int i = 0; i < 4; i++)
#pragma unroll
        for (int j = 0; j < 4; j++)
#pragma unroll
            for (int r = 0; r < 4; r++) c[i][j][r] = 0.f;

    const int ktiles = (K + 31) / 32;
    for (int kt = 0; kt < ktiles; kt++) {
        const int k0g = kt * 32;

        // ---- A tile: pairs [M][K], 4 bf16 per uint2 along k ----
#pragma unroll
        for (int it = 0; it < 4; it++) {
            int m  = (tid >> 3) + it * 32;
            int kc = (tid & 7) * 4;
            int gr = row0 + m, gk = k0g + kc;
            uint2 vh = make_uint2(0u, 0u), vl = make_uint2(0u, 0u);
            if (gr < M && gk < K) {
                vh = *(const uint2*)(Ah + (size_t)gr * K + gk);
                vl = *(const uint2*)(Al + (size_t)gr * K + gk);
            }
            *(uint2*)&AsH[m][kc >> 1] = vh;
            *(uint2*)&AsL[m][kc >> 1] = vl;
        }
        // ---- B tile ----
        if (BL == 0) {
#pragma unroll
            for (int it = 0; it < 4; it++) {
                int nn = (tid >> 3) + it * 32;
                int kc = (tid & 7) * 4;
                int gn = col0 + nn, gk = k0g + kc;
                uint2 vh = make_uint2(0u, 0u), vl = make_uint2(0u, 0u);
                if (gn < N && gk < K) {
                    vh = *(const uint2*)(Bh + (size_t)gn * K + gk);
                    vl = *(const uint2*)(Bl + (size_t)gn * K + gk);
                }
                *(uint2*)&BsH[nn][kc >> 1] = vh;
                *(uint2*)&BsL[nn][kc >> 1] = vl;
            }
        } else {
            int nn = tid & 127;
            int kq = (tid >> 7) * 16;       // 0 or 16
            int gn = col0 + nn;
            const unsigned short* Bhu = (const unsigned short*)Bh;
            const unsigned short* Blu = (const unsigned short*)Bl;
            unsigned ph[8], pl[8];
#pragma unroll
            for (int j = 0; j < 8; j++) {
                int k1 = k0g + kq + 2 * j, k2 = k1 + 1;
                unsigned short h1 = 0, h2 = 0, l1 = 0, l2 = 0;
                if (gn < N) {
                    if (k1 < K) { h1 = Bhu[(size_t)k1 * N + gn]; l1 = Blu[(size_t)k1 * N + gn]; }
                    if (k2 < K) { h2 = Bhu[(size_t)k2 * N + gn]; l2 = Blu[(size_t)k2 * N + gn]; }
                }
                ph[j] = ((unsigned)h2 << 16) | h1;
                pl[j] = ((unsigned)l2 << 16) | l1;
            }
            *(uint4*)&BsH[nn][(kq >> 1) + 0] = make_uint4(ph[0], ph[1], ph[2], ph[3]);
            *(uint4*)&BsH[nn][(kq >> 1) + 4] = make_uint4(ph[4], ph[5], ph[6], ph[7]);
            *(uint4*)&BsL[nn][(kq >> 1) + 0] = make_uint4(pl[0], pl[1], pl[2], pl[3]);
            *(uint4*)&BsL[nn][(kq >> 1) + 4] = make_uint4(pl[4], pl[5], pl[6], pl[7]);
        }
        __syncthreads();

#pragma unroll
        for (int step = 0; step < 2; step++) {   // two k16 steps
            const int kb = step * 8;
            unsigned aH[4][4], bH[4][2];
#pragma unroll
            for (int mt = 0; mt < 4; mt++) {
                int am = wm * 64 + mt * 16 + g;
                aH[mt][0] = AsH[am    ][kb + t];
                aH[mt][1] = AsH[am + 8][kb + t];
                aH[mt][2] = AsH[am    ][kb + t + 4];
                aH[mt][3] = AsH[am + 8][kb + t + 4];
            }
#pragma unroll
            for (int nt = 0; nt < 4; nt++) {
                int bn = wn * 32 + nt * 8 + g;
                bH[nt][0] = BsH[bn][kb + t];
                bH[nt][1] = BsH[bn][kb + t + 4];
            }
#define MMA_BF16(acc, A0, A1, A2, A3, B0, B1)                                   \
    asm volatile("mma.sync.aligned.m16n8k16.row.col.f32.bf16.bf16.f32 "         \
                 "{%0,%1,%2,%3}, {%4,%5,%6,%7}, {%8,%9}, {%0,%1,%2,%3};\n"      \
                 : "+f"(acc[0]), "+f"(acc[1]), "+f"(acc[2]), "+f"(acc[3])       \
                 : "r"(A0), "r"(A1), "r"(A2), "r"(A3), "r"(B0), "r"(B1))
            // hi * hi
#pragma unroll
            for (int mt = 0; mt < 4; mt++)
#pragma unroll
                for (int nt = 0; nt < 4; nt++)
                    MMA_BF16(c[mt][nt], aH[mt][0], aH[mt][1], aH[mt][2], aH[mt][3],
                             bH[nt][0], bH[nt][1]);
            // lo * hi
            {
                unsigned aL[4][4];
#pragma unroll
                for (int mt = 0; mt < 4; mt++) {
                    int am = wm * 64 + mt * 16 + g;
                    aL[mt][0] = AsL[am    ][kb + t];
                    aL[mt][1] = AsL[am + 8][kb + t];
                    aL[mt][2] = AsL[am    ][kb + t + 4];
                    aL[mt][3] = AsL[am + 8][kb + t + 4];
                }
#pragma unroll
                for (int mt = 0; mt < 4; mt++)
#pragma unroll
                    for (int nt = 0; nt < 4; nt++)
                        MMA_BF16(c[mt][nt], aL[mt][0], aL[mt][1], aL[mt][2], aL[mt][3],
                                 bH[nt][0], bH[nt][1]);
            }
            // hi * lo
            {
                unsigned bL[4][2];
#pragma unroll
                for (int nt = 0; nt < 4; nt++) {
                    int bn = wn * 32 + nt * 8 + g;
                    bL[nt][0] = BsL[bn][kb + t];
                    bL[nt][1] = BsL[bn][kb + t + 4];
                }
#pragma unroll
                for (int mt = 0; mt < 4; mt++)
#pragma unroll
                    for (int nt = 0; nt < 4; nt++)
                        MMA_BF16(c[mt][nt], aH[mt][0], aH[mt][1], aH[mt][2], aH[mt][3],
                                 bL[nt][0], bL[nt][1]);
            }
#undef MMA_BF16
        }
        __syncthreads();
    }

    // ---- epilogue ----
#pragma unroll
    for (int mt = 0; mt < 4; mt++) {
        int r = row0 + wm * 64 + mt * 16 + g;
#pragma unroll
        for (int nt = 0; nt < 4; nt++) {
            int cb = col0 + wn * 32 + nt * 8 + 2 * t;
#pragma unroll
            for (int half = 0; half < 2; half++) {
                int rr = r + half * 8;
                if (rr >= M || cb >= N) continue;
                float v0 = alpha * c[mt][nt][half * 2 + 0];
                float v1 = alpha * c[mt][nt][half * 2 + 1];
                if (OS) {
                    unsigned hi, lo;
                    split_pack2(v0, v1, hi, lo);
                    *(unsigned*)(Ch + (size_t)rr * N + cb) = hi;
                    *(unsigned*)(Cl + (size_t)rr * N + cb) = lo;
                } else {
                    if (bias)  { v0 += bias[cb]; v1 += bias[cb + 1]; }
                    if (resid) {
                        v0 += resid[(size_t)rr * N + cb];
                        v1 += resid[(size_t)rr * N + cb + 1];
                    }
                    C[(size_t)rr * N + cb]     = v0;
                    C[(size_t)rr * N + cb + 1] = v1;
                }
            }
        }
    }
}

// ---------------- fp32 SIMT GEMM (classifier only, exact) ---------------------
__global__ void __launch_bounds__(256) gemm_simt(
    const float* __restrict__ A, const float* __restrict__ B, float* __restrict__ C,
    int M, int N, int K, const float* __restrict__ bias)
{
    __shared__ float As[16][64];
    __shared__ float Bs[16][64];
    const int tid = threadIdx.x;
    const int tx = tid & 15, ty = tid >> 4;
    const int row0 = blockIdx.y * 64;
    const int col0 = blockIdx.x * 64;

    float acc[4][4];
#pragma unroll
    for (int i = 0; i < 4; i++)
#pragma unroll
        for (int j = 0; j < 4; j++) acc[i][j] = 0.f;

    const int lrow = tid >> 2, lk4 = (tid & 3) * 4;
    const int brow16 = tid >> 4, bcol4 = (tid & 15) * 4;

    for (int k0 = 0; k0 < K; k0 += 16) {
        float4 av = make_float4(0.f, 0.f, 0.f, 0.f);
        {
            int r = row0 + lrow, kc = k0 + lk4;
            if (r < M && kc < K) av = *(const float4*)(A + (size_t)r * K + kc);
        }
        As[lk4 + 0][lrow] = av.x; As[lk4 + 1][lrow] = av.y;
        As[lk4 + 2][lrow] = av.z; As[lk4 + 3][lrow] = av.w;

        float4 bv = make_float4(0.f, 0.f, 0.f, 0.f);
        {
            int kc = k0 + brow16, cc = col0 + bcol4;
            if (kc < K && cc < N) {
                if (cc + 3 < N) bv = *(const float4*)(B + (size_t)kc * N + cc);
                else {
                    bv.x = B[(size_t)kc * N + cc];
                    if (cc + 1 < N) bv.y = B[(size_t)kc * N + cc + 1];
                    if (cc + 2 < N) bv.z = B[(size_t)kc * N + cc + 2];
                }
            }
        }
        *(float4*)&Bs[brow16][bcol4] = bv;
        __syncthreads();

#pragma unroll
        for (int kk = 0; kk < 16; kk++) {
            float4 a = *(const float4*)&As[kk][ty * 4];
            float4 b = *(const float4*)&Bs[kk][tx * 4];
            acc[0][0] = fmaf(a.x, b.x, acc[0][0]); acc[0][1] = fmaf(a.x, b.y, acc[0][1]);
            acc[0][2] = fmaf(a.x, b.z, acc[0][2]); acc[0][3] = fmaf(a.x, b.w, acc[0][3]);
            acc[1][0] = fmaf(a.y, b.x, acc[1][0]); acc[1][1] = fmaf(a.y, b.y, acc[1][1]);
            acc[1][2] = fmaf(a.y, b.z, acc[1][2]); acc[1][3] = fmaf(a.y, b.w, acc[1][3]);
            acc[2][0] = fmaf(a.z, b.x, acc[2][0]); acc[2][1] = fmaf(a.z, b.y, acc[2][1]);
            acc[2][2] = fmaf(a.z, b.z, acc[2][2]); acc[2][3] = fmaf(a.z, b.w, acc[2][3]);
            acc[3][0] = fmaf(a.w, b.x, acc[3][0]); acc[3][1] = fmaf(a.w, b.y, acc[3][1]);
            acc[3][2] = fmaf(a.w, b.z, acc[3][2]); acc[3][3] = fmaf(a.w, b.w, acc[3][3]);
        }
        __syncthreads();
    }

#pragma unroll
    for (int i = 0; i < 4; i++) {
        int r = row0 + ty * 4 + i;
        if (r >= M) continue;
#pragma unroll
        for (int j = 0; j < 4; j++) {
            int cc = col0 + tx * 4 + j;
            if (cc >= N) continue;
            float v = acc[i][j];
            if (bias) v += bias[cc];
            C[(size_t)r * N + cc] = v;
        }
    }
}

// ---------------- launch -----------------------------------------------------
extern "C" void kernel_launch(void* const* d_in, const int* in_sizes, int n_in,
                              void* d_out, int out_size)
{
    const float* image  = (const float*)d_in[0];
    const float* ln1_g  = (const float*)d_in[1];
    const float* ln1_b  = (const float*)d_in[2];
    const float* W_emb  = (const float*)d_in[3];
    const float* b_emb  = (const float*)d_in[4];
    const float* ln2_g  = (const float*)d_in[5];
    const float* ln2_b  = (const float*)d_in[6];
    const float* pos    = (const float*)d_in[7];
    const float* norm_g = (const float*)d_in[8];
    const float* norm_b = (const float*)d_in[9];
    const float* WV     = (const float*)d_in[10];
    const float* WK     = (const float*)d_in[11];
    const float* WQ     = (const float*)d_in[12];
    const float* lastW  = (const float*)d_in[13];
    const float* lastb  = (const float*)d_in[14];
    float* out = (float*)d_out;

    float *px, *pxn, *pS, *pMean;
    __nv_bfloat16 *pph, *ppl, *pxnh, *pxnl, *pqh, *pql, *pkh, *pkl, *pGh, *pGl, *pAh, *pAl;
    __nv_bfloat16 *pWeth, *pWetl, *pWQth, *pWQtl, *pWKth, *pWKtl, *pWVth, *pWVtl;
    cudaGetSymbolAddress((void**)&px,    g_x);
    cudaGetSymbolAddress((void**)&pxn,   g_xn);
    cudaGetSymbolAddress((void**)&pS,    g_S);
    cudaGetSymbolAddress((void**)&pMean, g_mean);
    cudaGetSymbolAddress((void**)&pph,   g_ph);   cudaGetSymbolAddress((void**)&ppl,  g_pl);
    cudaGetSymbolAddress((void**)&pxnh,  g_xnh);  cudaGetSymbolAddress((void**)&pxnl, g_xnl);
    cudaGetSymbolAddress((void**)&pqh,   g_qh);   cudaGetSymbolAddress((void**)&pql,  g_ql);
    cudaGetSymbolAddress((void**)&pkh,   g_kh);   cudaGetSymbolAddress((void**)&pkl,  g_kl);
    cudaGetSymbolAddress((void**)&pGh,   g_Gh);   cudaGetSymbolAddress((void**)&pGl,  g_Gl);
    cudaGetSymbolAddress((void**)&pAh,   g_Ah);   cudaGetSymbolAddress((void**)&pAl,  g_Al);
    cudaGetSymbolAddress((void**)&pWeth, g_Weth); cudaGetSymbolAddress((void**)&pWetl, g_Wetl);
    cudaGetSymbolAddress((void**)&pWQth, g_WQth); cudaGetSymbolAddress((void**)&pWQtl, g_WQtl);
    cudaGetSymbolAddress((void**)&pWKth, g_WKth); cudaGetSymbolAddress((void**)&pWKtl, g_WKtl);
    cudaGetSymbolAddress((void**)&pWVth, g_WVth); cudaGetSymbolAddress((void**)&pWVtl, g_WVtl);

    const long long sQK = (long long)NPATCH * TDIM;
    const long long sAA = (long long)NPATCH * NPATCH;
    const float scale = 0.08838834764831845f;   // 128^-0.5

    // ---- weight prep (once per launch, reused 6x) ----
    split_transpose_kernel<<<dim3(32, 24), dim3(32, 8)>>>(W_emb, pWeth, pWetl, PDIM, TDIM);
    split_transpose_kernel<<<dim3(32, 32), dim3(32, 8)>>>(WQ, pWQth, pWQtl, TDIM, TDIM);
    split_transpose_kernel<<<dim3(32, 32), dim3(32, 8)>>>(WK, pWKth, pWKtl, TDIM, TDIM);
    split_transpose_kernel<<<dim3(4, 4),   dim3(32, 8)>>>(WV, pWVth, pWVtl, 128, 128);

    // ---- patchify + LN1 (split) ----
    patchify_ln_kernel<<<NROWS, 256>>>(image, ln1_g, ln1_b);
    // embed: patches(12544x768) @ W_emb + b_emb -> x (f32)
    gemm_bf3<0, false><<<dim3(8, 98, 1), 256>>>(pph, ppl, pWeth, pWetl,
        px, nullptr, nullptr, NROWS, TDIM, PDIM, 0, 0, 0, 1.f, b_emb, nullptr);
    // LN2 + pos -> x (in place, f32 only)
    ln1024_kernel<<<NROWS, 256>>>(px, px, ln2_g, ln2_b, pos, nullptr, nullptr);

    for (int l = 0; l < 6; l++) {
        // xn = LN(x): f32 + split pairs
        ln1024_kernel<<<NROWS, 256>>>(px, pxn, norm_g, norm_b, nullptr, pxnh, pxnl);
        // q = xn @ WQ, k = xn @ WK -> split pairs
        gemm_bf3<0, true><<<dim3(8, 98, 1), 256>>>(pxnh, pxnl, pWQth, pWQtl,
            nullptr, pqh, pql, NROWS, TDIM, TDIM, 0, 0, 0, 1.f, nullptr, nullptr);
        gemm_bf3<0, true><<<dim3(8, 98, 1), 256>>>(pxnh, pxnl, pWKth, pWKtl,
            nullptr, pkh, pkl, NROWS, TDIM, TDIM, 0, 0, 0, 1.f, nullptr, nullptr);
        // G = per-head xn @ WV -> split pairs  ((100352 x 128) @ (128 x 128))
        gemm_bf3<0, true><<<dim3(1, 784, 1), 256>>>(pxnh, pxnl, pWVth, pWVtl,
            nullptr, pGh, pGl, NROWS * 8, 128, 128, 0, 0, 0, 1.f, nullptr, nullptr);
        // S = scale * q @ k^T : k pairs are already [N][K]
        gemm_bf3<0, false><<<dim3(2, 2, BATCH), 256>>>(pqh, pql, pkh, pkl,
            pS, nullptr, nullptr, NPATCH, NPATCH, TDIM, sQK, sQK, sAA,
            scale, nullptr, nullptr);
        // A = softmax(S) -> split pairs
        softmax196_kernel<<<BATCH * NPATCH, 256>>>();
        // x = A @ G + xn   (G pairs are [K][N] row-major)
        gemm_bf3<1, false><<<dim3(8, 2, BATCH), 256>>>(pAh, pAl, pGh, pGl,
            px, nullptr, nullptr, NPATCH, TDIM, NPATCH, sAA, sQK, sQK,
            1.f, nullptr, pxn);
    }

    mean_kernel<<<BATCH, 256>>>();
    gemm_simt<<<dim3(16, 1, 1), 256>>>(pMean, lastW, out, BATCH, 1000, TDIM, lastb);
}

// round 9
// speedup vs baseline: 1.4135x; 1.4135x over previous
#include <cuda_runtime.h>
#include <cuda_bf16.h>
#include <stdint.h>
#include <math.h>

#define BATCH  64
#define NPATCH 196
#define NROWS  (BATCH * NPATCH)   // 12544
#define TDIM   1024
#define PDIM   768

// ---------------- scratch (static device allocations; no cudaMalloc) --------
__device__ float g_x [NROWS * TDIM];
__device__ float g_xn[NROWS * TDIM];
__device__ float g_S [BATCH * NPATCH * NPATCH];
__device__ float g_mean[BATCH * TDIM];

__device__ __nv_bfloat16 g_ph[NROWS * PDIM],  g_pl[NROWS * PDIM];
__device__ __nv_bfloat16 g_xnh[NROWS * TDIM], g_xnl[NROWS * TDIM];
__device__ __nv_bfloat16 g_th[NROWS * TDIM],  g_tl[NROWS * TDIM];   // t = xn @ (WQ WK^T)
__device__ __nv_bfloat16 g_Gh[NROWS * TDIM],  g_Gl[NROWS * TDIM];
__device__ __nv_bfloat16 g_Ah[BATCH * NPATCH * NPATCH], g_Al[BATCH * NPATCH * NPATCH];
// weight splits
__device__ __nv_bfloat16 g_Weth[TDIM * PDIM], g_Wetl[TDIM * PDIM];   // W_emb^T [N][K]
__device__ __nv_bfloat16 g_WVth[128 * 128],   g_WVtl[128 * 128];     // WV^T
__device__ __nv_bfloat16 g_WQsh[TDIM * TDIM], g_WQsl[TDIM * TDIM];   // WQ plain split
__device__ __nv_bfloat16 g_WKsh[TDIM * TDIM], g_WKsl[TDIM * TDIM];   // WK plain split
__device__ __nv_bfloat16 g_Mth[TDIM * TDIM],  g_Mtl[TDIM * TDIM];    // (WQ WK^T)^T pairs

// ---------------- helpers ----------------------------------------------------
__device__ __forceinline__ float warp_sum(float v) {
#pragma unroll
    for (int o = 16; o; o >>= 1) v += __shfl_xor_sync(0xffffffffu, v, o);
    return v;
}
__device__ __forceinline__ float warp_max(float v) {
#pragma unroll
    for (int o = 16; o; o >>= 1) v = fmaxf(v, __shfl_xor_sync(0xffffffffu, v, o));
    return v;
}
__device__ __forceinline__ void block_sum2(float& a, float& b, float* sm) {
    a = warp_sum(a);
    b = warp_sum(b);
    int w = threadIdx.x >> 5, l = threadIdx.x & 31;
    if (l == 0) { sm[w] = a; sm[8 + w] = b; }
    __syncthreads();
    float ta = 0.f, tb = 0.f;
#pragma unroll
    for (int i = 0; i < 8; i++) { ta += sm[i]; tb += sm[8 + i]; }
    a = ta; b = tb;
}
__device__ __forceinline__ void split1(float x, __nv_bfloat16& h, __nv_bfloat16& l) {
    h = __float2bfloat16_rn(x);
    l = __float2bfloat16_rn(x - __bfloat162float(h));
}
__device__ __forceinline__ void split_pack2(float a, float b, unsigned& hi, unsigned& lo) {
    __nv_bfloat16 ha, la, hb, lb;
    split1(a, ha, la);
    split1(b, hb, lb);
    hi = ((unsigned)__bfloat16_as_ushort(hb) << 16) | (unsigned)__bfloat16_as_ushort(ha);
    lo = ((unsigned)__bfloat16_as_ushort(lb) << 16) | (unsigned)__bfloat16_as_ushort(la);
}
__device__ __forceinline__ uint32_t smem_u32(const void* p) {
    uint32_t a;
    asm("{ .reg .u64 t; cvta.to.shared.u64 t, %1; cvt.u32.u64 %0, t; }" : "=r"(a) : "l"(p));
    return a;
}
__device__ __forceinline__ void ldsm_x4(uint32_t addr, unsigned& r0, unsigned& r1,
                                        unsigned& r2, unsigned& r3) {
    asm volatile("ldmatrix.sync.aligned.m8n8.x4.shared.b16 {%0,%1,%2,%3}, [%4];"
                 : "=r"(r0), "=r"(r1), "=r"(r2), "=r"(r3) : "r"(addr));
}

// ---------------- weight split + transpose: W[K][N] -> hi/lo [N][K] ----------
__global__ void split_transpose_kernel(const float* __restrict__ W,
                                       __nv_bfloat16* __restrict__ Wh,
                                       __nv_bfloat16* __restrict__ Wl,
                                       int K, int N) {
    __shared__ float t[32][33];
    int n0 = blockIdx.x * 32, k0 = blockIdx.y * 32;
    int x = threadIdx.x, y = threadIdx.y;
#pragma unroll
    for (int i = 0; i < 32; i += 8)
        t[y + i][x] = W[(size_t)(k0 + y + i) * N + n0 + x];
    __syncthreads();
#pragma unroll
    for (int i = 0; i < 32; i += 8) {
        int n = n0 + y + i, k = k0 + x;
        __nv_bfloat16 h, l;
        split1(t[x][y + i], h, l);
        Wh[(size_t)n * K + k] = h;
        Wl[(size_t)n * K + k] = l;
    }
}
// plain elementwise split
__global__ void split_plain_kernel(const float* __restrict__ W,
                                   __nv_bfloat16* __restrict__ Wh,
                                   __nv_bfloat16* __restrict__ Wl, int n) {
    int i = blockIdx.x * 256 + threadIdx.x;
    if (i < n) {
        __nv_bfloat16 h, l;
        split1(W[i], h, l);
        Wh[i] = h; Wl[i] = l;
    }
}

// ---------------- patchify + LayerNorm(768) -> split pairs -------------------
__global__ void patchify_ln_kernel(const float* __restrict__ img,
                                   const float* __restrict__ gam,
                                   const float* __restrict__ bet) {
    __shared__ float sv[PDIM];
    __shared__ float sred[16];
    int row = blockIdx.x;
    int b = row / NPATCH, n = row % NPATCH;
    int hp = n / 14, wp = n % 14;
    const float* base = img + (size_t)b * 3 * 224 * 224;
    int tid = threadIdx.x;
    float s = 0.f, s2 = 0.f;
#pragma unroll
    for (int i = 0; i < 3; i++) {
        int f = tid + i * 256;
        int p1 = f / 48, r = f % 48, p2 = r / 3, c = r % 3;
        float v = base[((size_t)c * 224 + hp * 16 + p1) * 224 + wp * 16 + p2];
        sv[f] = v; s += v; s2 += v * v;
    }
    block_sum2(s, s2, sred);
    float m = s * (1.f / 768.f);
    float rstd = rsqrtf(s2 * (1.f / 768.f) - m * m + 1e-5f);
#pragma unroll
    for (int i = 0; i < 3; i++) {
        int f = tid + i * 256;
        float v = (sv[f] - m) * rstd * gam[f] + bet[f];
        __nv_bfloat16 h, l;
        split1(v, h, l);
        g_ph[(size_t)row * PDIM + f] = h;
        g_pl[(size_t)row * PDIM + f] = l;
    }
}

// ---------------- LayerNorm(1024): f32 out + optional pos + optional pairs ---
__global__ void ln1024_kernel(const float* __restrict__ in, float* __restrict__ out,
                              const float* __restrict__ gam, const float* __restrict__ bet,
                              const float* __restrict__ pos,
                              __nv_bfloat16* __restrict__ oh, __nv_bfloat16* __restrict__ ol) {
    __shared__ float sred[16];
    int row = blockIdx.x, tid = threadIdx.x;
    const float4* ip = (const float4*)(in + (size_t)row * TDIM);
    float4 v = ip[tid];
    float s  = v.x + v.y + v.z + v.w;
    float s2 = v.x * v.x + v.y * v.y + v.z * v.z + v.w * v.w;
    block_sum2(s, s2, sred);
    float m = s * (1.f / 1024.f);
    float rstd = rsqrtf(s2 * (1.f / 1024.f) - m * m + 1e-5f);
    float4 gg = ((const float4*)gam)[tid];
    float4 bb = ((const float4*)bet)[tid];
    float4 o;
    o.x = (v.x - m) * rstd * gg.x + bb.x;
    o.y = (v.y - m) * rstd * gg.y + bb.y;
    o.z = (v.z - m) * rstd * gg.z + bb.z;
    o.w = (v.w - m) * rstd * gg.w + bb.w;
    if (pos) {
        int n = row % NPATCH;
        float4 p = ((const float4*)(pos + (size_t)n * TDIM))[tid];
        o.x += p.x; o.y += p.y; o.z += p.z; o.w += p.w;
    }
    ((float4*)(out + (size_t)row * TDIM))[tid] = o;
    if (oh) {
        unsigned h01, l01, h23, l23;
        split_pack2(o.x, o.y, h01, l01);
        split_pack2(o.z, o.w, h23, l23);
        ((uint2*)(oh + (size_t)row * TDIM))[tid] = make_uint2(h01, h23);
        ((uint2*)(ol + (size_t)row * TDIM))[tid] = make_uint2(l01, l23);
    }
}

// ---------------- softmax over 196, writes split pairs ------------------------
__global__ void softmax196_kernel() {
    __shared__ float sred[16];
    int row = blockIdx.x, tid = threadIdx.x;
    const float* p = g_S + (size_t)row * NPATCH;
    float v = (tid < NPATCH) ? p[tid] : -1e30f;
    float mx = warp_max(v);
    int w = tid >> 5, l = tid & 31;
    if (l == 0) sred[w] = mx;
    __syncthreads();
    float bm = -1e30f;
#pragma unroll
    for (int i = 0; i < 8; i++) bm = fmaxf(bm, sred[i]);
    float e = (tid < NPATCH) ? expf(v - bm) : 0.f;
    __syncthreads();
    float s = warp_sum(e);
    if (l == 0) sred[w] = s;
    __syncthreads();
    float bs = 0.f;
#pragma unroll
    for (int i = 0; i < 8; i++) bs += sred[i];
    if (tid < NPATCH) {
        float a = e / bs;
        __nv_bfloat16 h, lo;
        split1(a, h, lo);
        g_Ah[(size_t)row * NPATCH + tid] = h;
        g_Al[(size_t)row * NPATCH + tid] = lo;
    }
}

// ---------------- mean over tokens --------------------------------------------
__global__ void mean_kernel() {
    int b = blockIdx.x, tid = threadIdx.x;
    const float4* xp = (const float4*)(g_x + (size_t)b * NPATCH * TDIM);
    float4 acc = make_float4(0.f, 0.f, 0.f, 0.f);
    for (int n = 0; n < NPATCH; n++) {
        float4 v = xp[(size_t)n * 256 + tid];
        acc.x += v.x; acc.y += v.y; acc.z += v.z; acc.w += v.w;
    }
    const float inv = 1.f / 196.f;
    ((float4*)(g_mean + (size_t)b * TDIM))[tid] =
        make_float4(acc.x * inv, acc.y * inv, acc.z * inv, acc.w * inv);
}

// ---------------- bf16x3 mma.sync GEMM with ldmatrix fragments ----------------
// C = alpha * (Ah+Al)(MxK) @ (Bh+Bl) + bias + resid   (drop lo*lo term)
// BL=0: B pairs are [N][K] row-major. BL=1: B pairs are [K][N] row-major.
// OS: write split bf16 pairs to Ch/Cl instead of f32 C.
// block tile 128x128x32, 256 threads = 8 warps (2x4), warp tile 64x32.
template <int BL, bool OS>
__global__ void __launch_bounds__(256, 2) gemm_bf3(
    const __nv_bfloat16* __restrict__ Ah, const __nv_bfloat16* __restrict__ Al,
    const __nv_bfloat16* __restrict__ Bh, const __nv_bfloat16* __restrict__ Bl,
    float* __restrict__ C, __nv_bfloat16* __restrict__ Ch, __nv_bfloat16* __restrict__ Cl,
    int M, int N, int K,
    long long sA, long long sB, long long sC,
    float alpha, const float* __restrict__ bias, const float* __restrict__ resid)
{
    // rows of 32 k (=16 u32) padded to 20 u32; stride 80B => ldmatrix conflict-free
    __shared__ __align__(16) unsigned AsH[128][20], AsL[128][20];
    __shared__ __align__(16) unsigned BsH[128][20], BsL[128][20];

    const int bz = blockIdx.z;
    Ah += (size_t)bz * sA;  Al += (size_t)bz * sA;
    Bh += (size_t)bz * sB;  Bl += (size_t)bz * sB;
    if (!OS) { C += (size_t)bz * sC; if (resid) resid += (size_t)bz * sC; }
    else     { Ch += (size_t)bz * sC; Cl += (size_t)bz * sC; }

    const int tid  = threadIdx.x;
    const int lane = tid & 31, warp = tid >> 5;
    const int wm = warp >> 2, wn = warp & 3;
    const int g = lane >> 2, t = lane & 3;

    const int row0 = blockIdx.y * 128;
    const int col0 = blockIdx.x * 128;

    const uint32_t aHb = smem_u32(&AsH[0][0]), aLb = smem_u32(&AsL[0][0]);
    const uint32_t bHb = smem_u32(&BsH[0][0]), bLb = smem_u32(&BsL[0][0]);

    // ldmatrix lane->address precomputed pieces
    const int lq = lane >> 3, lr = lane & 7;
    const int a_row = ((lq & 1) << 3) + lr;          // row offset within m16 tile
    const uint32_t a_kb = (uint32_t)(((lq >> 1) << 3) * 2);   // 0 or 16 bytes
    const int b_row = ((lq >> 1) << 3) + lr;         // row offset within n16 pair
    const uint32_t b_kb = (uint32_t)(((lq & 1) << 3) * 2);

    float c[4][4][4];
#pragma unroll
    for (int i = 0; i < 4; i++)
#pragma unroll
        for (int j = 0; j < 4; j++)
#pragma unroll
            for (int r = 0; r < 4; r++) c[i][j][r] = 0.f;

    const int ktiles = (K + 31) / 32;
    for (int kt = 0; kt < ktiles; kt++) {
        const int k0g = kt * 32;
        // ---- A tile loader (pairs [M][K]) ----
#pragma unroll
        for (int it = 0; it < 4; it++) {
            int m  = (tid >> 3) + it * 32;
            int kc = (tid & 7) * 4;
            int gr = row0 + m, gk = k0g + kc;
            uint2 vh = make_uint2(0u, 0u), vl = make_uint2(0u, 0u);
            if (gr < M && gk < K) {
                vh = *(const uint2*)(Ah + (size_t)gr * K + gk);
                vl = *(const uint2*)(Al + (size_t)gr * K + gk);
            }
            *(uint2*)&AsH[m][kc >> 1] = vh;
            *(uint2*)&AsL[m][kc >> 1] = vl;
        }
        // ---- B tile loader ----
        if (BL == 0) {
#pragma unroll
            for (int it = 0; it < 4; it++) {
                int nn = (tid >> 3) + it * 32;
                int kc = (tid & 7) * 4;
                int gn = col0 + nn, gk = k0g + kc;
                uint2 vh = make_uint2(0u, 0u), vl = make_uint2(0u, 0u);
                if (gn < N && gk < K) {
                    vh = *(const uint2*)(Bh + (size_t)gn * K + gk);
                    vl = *(const uint2*)(Bl + (size_t)gn * K + gk);
                }
                *(uint2*)&BsH[nn][kc >> 1] = vh;
                *(uint2*)&BsL[nn][kc >> 1] = vl;
            }
        } else {
            int nn = tid & 127;
            int kq = (tid >> 7) * 16;
            int gn = col0 + nn;
            const unsigned short* Bhu = (const unsigned short*)Bh;
            const unsigned short* Blu = (const unsigned short*)Bl;
            unsigned ph[8], pl[8];
#pragma unroll
            for (int j = 0; j < 8; j++) {
                int k1 = k0g + kq + 2 * j, k2 = k1 + 1;
                unsigned short h1 = 0, h2 = 0, l1 = 0, l2 = 0;
                if (gn < N) {
                    if (k1 < K) { h1 = Bhu[(size_t)k1 * N + gn]; l1 = Blu[(size_t)k1 * N + gn]; }
                    if (k2 < K) { h2 = Bhu[(size_t)k2 * N + gn]; l2 = Blu[(size_t)k2 * N + gn]; }
                }
                ph[j] = ((unsigned)h2 << 16) | h1;
                pl[j] = ((unsigned)l2 << 16) | l1;
            }
            *(uint4*)&BsH[nn][(kq >> 1) + 0] = make_uint4(ph[0], ph[1], ph[2], ph[3]);
            *(uint4*)&BsH[nn][(kq >> 1) + 4] = make_uint4(ph[4], ph[5], ph[6], ph[7]);
            *(uint4*)&BsL[nn][(kq >> 1) + 0] = make_uint4(pl[0], pl[1], pl[2], pl[3]);
            *(uint4*)&BsL[nn][(kq >> 1) + 4] = make_uint4(pl[4], pl[5], pl[6], pl[7]);
        }
        __syncthreads();

#pragma unroll
        for (int step = 0; step < 2; step++) {
            const uint32_t kbase = (uint32_t)(step * 32);   // bytes into row
#define MMA_BF16(acc, A0, A1, A2, A3, B0, B1)                                   \
    asm volatile("mma.sync.aligned.m16n8k16.row.col.f32.bf16.bf16.f32 "         \
                 "{%0,%1,%2,%3}, {%4,%5,%6,%7}, {%8,%9}, {%0,%1,%2,%3};\n"      \
                 : "+f"(acc[0]), "+f"(acc[1]), "+f"(acc[2]), "+f"(acc[3])       \
                 : "r"(A0), "r"(A1), "r"(A2), "r"(A3), "r"(B0), "r"(B1))
            unsigned aH[4][4], bH[4][2], bL[4][2];
            // A hi frags (ldmatrix.x4: one per m16 tile)
#pragma unroll
            for (int mt = 0; mt < 4; mt++) {
                uint32_t ad = aHb + (uint32_t)(wm * 64 + mt * 16 + a_row) * 80 + kbase + a_kb;
                ldsm_x4(ad, aH[mt][0], aH[mt][1], aH[mt][2], aH[mt][3]);
            }
            // B hi frags (x4 covers two n8 tiles)
#pragma unroll
            for (int p = 0; p < 2; p++) {
                uint32_t ad = bHb + (uint32_t)(wn * 32 + p * 16 + b_row) * 80 + kbase + b_kb;
                unsigned r0, r1, r2, r3;
                ldsm_x4(ad, r0, r1, r2, r3);
                bH[2 * p][0] = r0; bH[2 * p][1] = r1;
                bH[2 * p + 1][0] = r2; bH[2 * p + 1][1] = r3;
            }
            // hi*hi
#pragma unroll
            for (int mt = 0; mt < 4; mt++)
#pragma unroll
                for (int nt = 0; nt < 4; nt++)
                    MMA_BF16(c[mt][nt], aH[mt][0], aH[mt][1], aH[mt][2], aH[mt][3],
                             bH[nt][0], bH[nt][1]);
            // B lo frags, hi*lo
#pragma unroll
            for (int p = 0; p < 2; p++) {
                uint32_t ad = bLb + (uint32_t)(wn * 32 + p * 16 + b_row) * 80 + kbase + b_kb;
                unsigned r0, r1, r2, r3;
                ldsm_x4(ad, r0, r1, r2, r3);
                bL[2 * p][0] = r0; bL[2 * p][1] = r1;
                bL[2 * p + 1][0] = r2; bL[2 * p + 1][1] = r3;
            }
#pragma unroll
            for (int mt = 0; mt < 4; mt++)
#pragma unroll
                for (int nt = 0; nt < 4; nt++)
                    MMA_BF16(c[mt][nt], aH[mt][0], aH[mt][1], aH[mt][2], aH[mt][3],
                             bL[nt][0], bL[nt][1]);
            // A lo frags, lo*hi
#pragma unroll
            for (int mt = 0; mt < 4; mt++) {
                unsigned a0, a1, a2, a3;
                uint32_t ad = aLb + (uint32_t)(wm * 64 + mt * 16 + a_row) * 80 + kbase + a_kb;
                ldsm_x4(ad, a0, a1, a2, a3);
#pragma unroll
                for (int nt = 0; nt < 4; nt++)
                    MMA_BF16(c[mt][nt], a0, a1, a2, a3, bH[nt][0], bH[nt][1]);
            }
#undef MMA_BF16
        }
        __syncthreads();
    }

    // ---- epilogue ----
#pragma unroll
    for (int mt = 0; mt < 4; mt++) {
        int r = row0 + wm * 64 + mt * 16 + g;
#pragma unroll
        for (int nt = 0; nt < 4; nt++) {
            int cb = col0 + wn * 32 + nt * 8 + 2 * t;
#pragma unroll
            for (int half = 0; half < 2; half++) {
                int rr = r + half * 8;
                if (rr >= M || cb >= N) continue;
                float v0 = alpha * c[mt][nt][half * 2 + 0];
                float v1 = alpha * c[mt][nt][half * 2 + 1];
                if (OS) {
                    unsigned hi, lo;
                    split_pack2(v0, v1, hi, lo);
                    *(unsigned*)(Ch + (size_t)rr * N + cb) = hi;
                    *(unsigned*)(Cl + (size_t)rr * N + cb) = lo;
                } else {
                    if (bias)  { v0 += bias[cb]; v1 += bias[cb + 1]; }
                    if (resid) {
                        v0 += resid[(size_t)rr * N + cb];
                        v1 += resid[(size_t)rr * N + cb + 1];
                    }
                    C[(size_t)rr * N + cb]     = v0;
                    C[(size_t)rr * N + cb + 1] = v1;
                }
            }
        }
    }
}

// ---------------- fp32 SIMT GEMM (classifier only, exact) ---------------------
__global__ void __launch_bounds__(256) gemm_simt(
    const float* __restrict__ A, const float* __restrict__ B, float* __restrict__ C,
    int M, int N, int K, const float* __restrict__ bias)
{
    __shared__ float As[16][64];
    __shared__ float Bs[16][64];
    const int tid = threadIdx.x;
    const int tx = tid & 15, ty = tid >> 4;
    const int row0 = blockIdx.y * 64;
    const int col0 = blockIdx.x * 64;

    float acc[4][4];
#pragma unroll
    for (int i = 0; i < 4; i++)
#pragma unroll
        for (int j = 0; j < 4; j++) acc[i][j] = 0.f;

    const int lrow = tid >> 2, lk4 = (tid & 3) * 4;
    const int brow16 = tid >> 4, bcol4 = (tid & 15) * 4;

    for (int k0 = 0; k0 < K; k0 += 16) {
        float4 av = make_float4(0.f, 0.f, 0.f, 0.f);
        {
            int r = row0 + lrow, kc = k0 + lk4;
            if (r < M && kc < K) av = *(const float4*)(A + (size_t)r * K + kc);
        }
        As[lk4 + 0][lrow] = av.x; As[lk4 + 1][lrow] = av.y;
        As[lk4 + 2][lrow] = av.z; As[lk4 + 3][lrow] = av.w;

        float4 bv = make_float4(0.f, 0.f, 0.f, 0.f);
        {
            int kc = k0 + brow16, cc = col0 + bcol4;
            if (kc < K && cc < N) {
                if (cc + 3 < N) bv = *(const float4*)(B + (size_t)kc * N + cc);
                else {
                    bv.x = B[(size_t)kc * N + cc];
                    if (cc + 1 < N) bv.y = B[(size_t)kc * N + cc + 1];
                    if (cc + 2 < N) bv.z = B[(size_t)kc * N + cc + 2];
                }
            }
        }
        *(float4*)&Bs[brow16][bcol4] = bv;
        __syncthreads();

#pragma unroll
        for (int kk = 0; kk < 16; kk++) {
            float4 a = *(const float4*)&As[kk][ty * 4];
            float4 b = *(const float4*)&Bs[kk][tx * 4];
            acc[0][0] = fmaf(a.x, b.x, acc[0][0]); acc[0][1] = fmaf(a.x, b.y, acc[0][1]);
            acc[0][2] = fmaf(a.x, b.z, acc[0][2]); acc[0][3] = fmaf(a.x, b.w, acc[0][3]);
            acc[1][0] = fmaf(a.y, b.x, acc[1][0]); acc[1][1] = fmaf(a.y, b.y, acc[1][1]);
            acc[1][2] = fmaf(a.y, b.z, acc[1][2]); acc[1][3] = fmaf(a.y, b.w, acc[1][3]);
            acc[2][0] = fmaf(a.z, b.x, acc[2][0]); acc[2][1] = fmaf(a.z, b.y, acc[2][1]);
            acc[2][2] = fmaf(a.z, b.z, acc[2][2]); acc[2][3] = fmaf(a.z, b.w, acc[2][3]);
            acc[3][0] = fmaf(a.w, b.x, acc[3][0]); acc[3][1] = fmaf(a.w, b.y, acc[3][1]);
            acc[3][2] = fmaf(a.w, b.z, acc[3][2]); acc[3][3] = fmaf(a.w, b.w, acc[3][3]);
        }
        __syncthreads();
    }

#pragma unroll
    for (int i = 0; i < 4; i++) {
        int r = row0 + ty * 4 + i;
        if (r >= M) continue;
#pragma unroll
        for (int j = 0; j < 4; j++) {
            int cc = col0 + tx * 4 + j;
            if (cc >= N) continue;
            float v = acc[i][j];
            if (bias) v += bias[cc];
            C[(size_t)r * N + cc] = v;
        }
    }
}

// ---------------- launch -----------------------------------------------------
extern "C" void kernel_launch(void* const* d_in, const int* in_sizes, int n_in,
                              void* d_out, int out_size)
{
    const float* image  = (const float*)d_in[0];
    const float* ln1_g  = (const float*)d_in[1];
    const float* ln1_b  = (const float*)d_in[2];
    const float* W_emb  = (const float*)d_in[3];
    const float* b_emb  = (const float*)d_in[4];
    const float* ln2_g  = (const float*)d_in[5];
    const float* ln2_b  = (const float*)d_in[6];
    const float* pos    = (const float*)d_in[7];
    const float* norm_g = (const float*)d_in[8];
    const float* norm_b = (const float*)d_in[9];
    const float* WV     = (const float*)d_in[10];
    const float* WK     = (const float*)d_in[11];
    const float* WQ     = (const float*)d_in[12];
    const float* lastW  = (const float*)d_in[13];
    const float* lastb  = (const float*)d_in[14];
    float* out = (float*)d_out;

    float *px, *pxn, *pS, *pMean;
    __nv_bfloat16 *pph, *ppl, *pxnh, *pxnl, *pth, *ptl, *pGh, *pGl, *pAh, *pAl;
    __nv_bfloat16 *pWeth, *pWetl, *pWVth, *pWVtl;
    __nv_bfloat16 *pWQsh, *pWQsl, *pWKsh, *pWKsl, *pMth, *pMtl;
    cudaGetSymbolAddress((void**)&px,    g_x);
    cudaGetSymbolAddress((void**)&pxn,   g_xn);
    cudaGetSymbolAddress((void**)&pS,    g_S);
    cudaGetSymbolAddress((void**)&pMean, g_mean);
    cudaGetSymbolAddress((void**)&pph,   g_ph);   cudaGetSymbolAddress((void**)&ppl,  g_pl);
    cudaGetSymbolAddress((void**)&pxnh,  g_xnh);  cudaGetSymbolAddress((void**)&pxnl, g_xnl);
    cudaGetSymbolAddress((void**)&pth,   g_th);   cudaGetSymbolAddress((void**)&ptl,  g_tl);
    cudaGetSymbolAddress((void**)&pGh,   g_Gh);   cudaGetSymbolAddress((void**)&pGl,  g_Gl);
    cudaGetSymbolAddress((void**)&pAh,   g_Ah);   cudaGetSymbolAddress((void**)&pAl,  g_Al);
    cudaGetSymbolAddress((void**)&pWeth, g_Weth); cudaGetSymbolAddress((void**)&pWetl, g_Wetl);
    cudaGetSymbolAddress((void**)&pWVth, g_WVth); cudaGetSymbolAddress((void**)&pWVtl, g_WVtl);
    cudaGetSymbolAddress((void**)&pWQsh, g_WQsh); cudaGetSymbolAddress((void**)&pWQsl, g_WQsl);
    cudaGetSymbolAddress((void**)&pWKsh, g_WKsh); cudaGetSymbolAddress((void**)&pWKsl, g_WKsl);
    cudaGetSymbolAddress((void**)&pMth,  g_Mth);  cudaGetSymbolAddress((void**)&pMtl,  g_Mtl);

    const long long sQK = (long long)NPATCH * TDIM;
    const long long sAA = (long long)NPATCH * NPATCH;
    const float scale = 0.08838834764831845f;   // 128^-0.5

    // ---- weight prep (once per launch, reused 6x) ----
    split_transpose_kernel<<<dim3(32, 24), dim3(32, 8)>>>(W_emb, pWeth, pWetl, PDIM, TDIM);
    split_transpose_kernel<<<dim3(4, 4),   dim3(32, 8)>>>(WV, pWVth, pWVtl, 128, 128);
    split_plain_kernel<<<4096, 256>>>(WQ, pWQsh, pWQsl, TDIM * TDIM);
    split_plain_kernel<<<4096, 256>>>(WK, pWKsh, pWKsl, TDIM * TDIM);
    // MT[f][e] = sum_d WK[f][d] * WQ[e][d]  == (WQ WK^T)^T, as split pairs [f][e]
    gemm_bf3<0, true><<<dim3(8, 8, 1), 256>>>(pWKsh, pWKsl, pWQsh, pWQsl,
        nullptr, pMth, pMtl, TDIM, TDIM, TDIM, 0, 0, 0, 1.f, nullptr, nullptr);

    // ---- patchify + LN1 (split) ----
    patchify_ln_kernel<<<NROWS, 256>>>(image, ln1_g, ln1_b);
    // embed: x = patches @ W_emb + b_emb (f32)
    gemm_bf3<0, false><<<dim3(8, 98, 1), 256>>>(pph, ppl, pWeth, pWetl,
        px, nullptr, nullptr, NROWS, TDIM, PDIM, 0, 0, 0, 1.f, b_emb, nullptr);
    // LN2 + pos -> x (in place)
    ln1024_kernel<<<NROWS, 256>>>(px, px, ln2_g, ln2_b, pos, nullptr, nullptr);

    for (int l = 0; l < 6; l++) {
        // xn = LN(x): f32 + split pairs
        ln1024_kernel<<<NROWS, 256>>>(px, pxn, norm_g, norm_b, nullptr, pxnh, pxnl);
        // t = xn @ (WQ WK^T)  (B = MT pairs [f][e] row-major = [N][K])
        gemm_bf3<0, true><<<dim3(8, 98, 1), 256>>>(pxnh, pxnl, pMth, pMtl,
            nullptr, pth, ptl, NROWS, TDIM, TDIM, 0, 0, 0, 1.f, nullptr, nullptr);
        // G = per-head xn @ WV  ((100352 x 128) @ (128 x 128))
        gemm_bf3<0, true><<<dim3(1, 784, 1), 256>>>(pxnh, pxnl, pWVth, pWVtl,
            nullptr, pGh, pGl, NROWS * 8, 128, 128, 0, 0, 0, 1.f, nullptr, nullptr);
        // S = scale * t @ xn^T   (B = xn pairs [N][K], batched)
        gemm_bf3<0, false><<<dim3(2, 2, BATCH), 256>>>(pth, ptl, pxnh, pxnl,
            pS, nullptr, nullptr, NPATCH, NPATCH, TDIM, sQK, sQK, sAA,
            scale, nullptr, nullptr);
        softmax196_kernel<<<BATCH * NPATCH, 256>>>();
        // x = A @ G + xn   (G pairs are [K][N] row-major)
        gemm_bf3<1, false><<<dim3(8, 2, BATCH), 256>>>(pAh, pAl, pGh, pGl,
            px, nullptr, nullptr, NPATCH, TDIM, NPATCH, sAA, sQK, sQK,
            1.f, nullptr, pxn);
    }

    mean_kernel<<<BATCH, 256>>>();
    gemm_simt<<<dim3(16, 1, 1), 256>>>(pMean, lastW, out, BATCH, 1000, TDIM, lastb);
}